// round 15
// baseline (speedup 1.0000x reference)
#include <cuda_runtime.h>
#include <cuda_bf16.h>
#include <math.h>
#include <stdint.h>

#define BATCH 2048
#define HDIM  4096
#define NHEAD 4
#define HSZ   1024

#define BM 64
#define BN 64
#define BK 32              // fp32 elems per K-chunk (128B data rows)
#define NTHR 128           // 4 warps, 32x32 per warp, 4 gates

#define TSTRIDE 144        // 128B data + 16B pad; LDSM conflict-free
#define TILE_B  (64 * TSTRIDE)               // 9216
#define STAGE_B (5 * TILE_B)                 // A + 4x B = 46080
#define SMEM_B  (2 * STAGE_B)                // 92160 (x2 CTAs/SM = 180KB)

#define OFF_A 0
#define OFF_B TILE_B

// ---------------- scratch (device globals; no runtime allocation) ----------
__device__ __align__(16) float g_xn   [(size_t)BATCH * HDIM];
__device__ __align__(16) float g_xact [(size_t)BATCH * HDIM];

// ---------------- helpers ---------------------------------------------------
__device__ __forceinline__ float warpSum(float v) {
#pragma unroll
    for (int o = 16; o > 0; o >>= 1) v += __shfl_down_sync(0xffffffffu, v, o);
    return v;
}

__device__ __forceinline__ uint32_t smem_u32(const void* p) {
    uint32_t a;
    asm("{ .reg .u64 t; cvta.to.shared.u64 t, %1; cvt.u32.u64 %0, t; }"
        : "=r"(a) : "l"(p));
    return a;
}

__device__ __forceinline__ void cp16(uint32_t saddr, const void* gaddr) {
    asm volatile("cp.async.cg.shared.global [%0], [%1], 16;"
                 :: "r"(saddr), "l"(gaddr));
}

__device__ __forceinline__ float tf32r(float x) {
    uint32_t u;
    asm("cvt.rna.tf32.f32 %0, %1;" : "=r"(u) : "f"(x));
    return __uint_as_float(u);
}

__device__ __forceinline__ void tf32r4(uint32_t* r) {
#pragma unroll
    for (int i = 0; i < 4; i++)
        asm("cvt.rna.tf32.f32 %0, %1;" : "=r"(r[i]) : "f"(__uint_as_float(r[i])));
}

__device__ __forceinline__ void ldsm4(uint32_t* r, uint32_t a) {
    asm volatile("ldmatrix.sync.aligned.m8n8.x4.shared.b16 {%0,%1,%2,%3}, [%4];"
                 : "=r"(r[0]), "=r"(r[1]), "=r"(r[2]), "=r"(r[3]) : "r"(a));
}

__device__ __forceinline__ void mma_tf32(float* c, uint32_t a0, uint32_t a1,
                                         uint32_t a2, uint32_t a3,
                                         uint32_t b0, uint32_t b1) {
    asm volatile(
        "mma.sync.aligned.m16n8k8.row.col.f32.tf32.tf32.f32 "
        "{%0,%1,%2,%3}, {%4,%5,%6,%7}, {%8,%9}, {%0,%1,%2,%3};"
        : "+f"(c[0]), "+f"(c[1]), "+f"(c[2]), "+f"(c[3])
        : "r"(a0), "r"(a1), "r"(a2), "r"(a3), "r"(b0), "r"(b1));
}

// gate elementwise math (identical formulas to previous gate_kernel)
__device__ __forceinline__ void slstm1(float iv, float fv, float zv, float ov,
                                       float cv, float nv, float mv,
                                       float& y, float& cn, float& nn, float& mn)
{
    float lsf  = fminf(fv, 0.f) - log1pf(expf(-fabsf(fv)));
    float lfm  = mv + lsf;
    float mnew = fmaxf(iv, lfm);
    float ig = expf(iv  - mnew);
    float fg = expf(lfm - mnew);
    cn = fg * cv + ig * tanhf(zv);
    nn = fg * nv + ig;
    float so = 1.f / (1.f + expf(-ov));
    y  = so * cn / (nn + 1e-6f);
    mn = mnew;
}

// ---------------- Kernel A: layernorm + conv + silu + tf32 emit ------------
__global__ __launch_bounds__(256) void ln_conv_kernel(
    const float* __restrict__ x, const float* __restrict__ cs,
    const float* __restrict__ ln_w, const float* __restrict__ conv_w,
    const float* __restrict__ conv_b, float* __restrict__ out_ncs)
{
    const int b   = blockIdx.x;
    const int tid = threadIdx.x;
    const float* xr = x + (size_t)b * HDIM;

    float4 xv[4];
    float s = 0.f, sq = 0.f;
#pragma unroll
    for (int i = 0; i < 4; i++) {
        xv[i] = *(const float4*)(xr + (size_t)(tid + i * 256) * 4);
        s  += xv[i].x + xv[i].y + xv[i].z + xv[i].w;
        sq += xv[i].x * xv[i].x + xv[i].y * xv[i].y + xv[i].z * xv[i].z + xv[i].w * xv[i].w;
    }
    __shared__ float rs[8], rq[8];
    float ws = warpSum(s), wq = warpSum(sq);
    if ((tid & 31) == 0) { rs[tid >> 5] = ws; rq[tid >> 5] = wq; }
    __syncthreads();
    float ts = 0.f, tq = 0.f;
#pragma unroll
    for (int i = 0; i < 8; i++) { ts += rs[i]; tq += rq[i]; }
    const float mean = ts * (1.f / HDIM);
    const float var  = tq * (1.f / HDIM) - mean * mean;
    const float rstd = rsqrtf(var + 1e-5f);

    const float* csb = cs      + (size_t)b * 3 * HDIM;
    float*       ncs = out_ncs + (size_t)b * 3 * HDIM;

#pragma unroll
    for (int i = 0; i < 4; i++) {
        const int c = (tid + i * 256) * 4;
        float4 lw = *(const float4*)(ln_w + c);
        float4 xn;
        xn.x = (xv[i].x - mean) * rstd * lw.x;
        xn.y = (xv[i].y - mean) * rstd * lw.y;
        xn.z = (xv[i].z - mean) * rstd * lw.z;
        xn.w = (xv[i].w - mean) * rstd * lw.w;

        float4 c0 = *(const float4*)(csb + c);
        float4 c1 = *(const float4*)(csb + HDIM + c);
        float4 c2 = *(const float4*)(csb + 2 * HDIM + c);
        float4 cb = *(const float4*)(conv_b + c);
        float4 w0 = *(const float4*)(conv_w + (size_t)(c + 0) * 4);
        float4 w1 = *(const float4*)(conv_w + (size_t)(c + 1) * 4);
        float4 w2 = *(const float4*)(conv_w + (size_t)(c + 2) * 4);
        float4 w3 = *(const float4*)(conv_w + (size_t)(c + 3) * 4);

        float4 xc;
        xc.x = c0.x * w0.x + c1.x * w0.y + c2.x * w0.z + xn.x * w0.w + cb.x;
        xc.y = c0.y * w1.x + c1.y * w1.y + c2.y * w1.z + xn.y * w1.w + cb.y;
        xc.z = c0.z * w2.x + c1.z * w2.y + c2.z * w2.z + xn.z * w2.w + cb.z;
        xc.w = c0.w * w3.x + c1.w * w3.y + c2.w * w3.z + xn.w * w3.w + cb.w;

        float4 xa;
        xa.x = xc.x / (1.f + expf(-xc.x));
        xa.y = xc.y / (1.f + expf(-xc.y));
        xa.z = xc.z / (1.f + expf(-xc.z));
        xa.w = xc.w / (1.f + expf(-xc.w));

        float4 xnr, xar;
        xnr.x = tf32r(xn.x); xnr.y = tf32r(xn.y); xnr.z = tf32r(xn.z); xnr.w = tf32r(xn.w);
        xar.x = tf32r(xa.x); xar.y = tf32r(xa.y); xar.z = tf32r(xa.z); xar.w = tf32r(xa.w);

        const size_t off = (size_t)b * HDIM + c;
        *(float4*)(g_xn   + off) = xnr;
        *(float4*)(g_xact + off) = xar;

        *(float4*)(ncs + c)            = c1;
        *(float4*)(ncs + HDIM + c)     = c2;
        *(float4*)(ncs + 2 * HDIM + c) = xn;
    }
}

// ---------------- fused GEMM compute chunk (compile-time gate set) ----------
template<int NG, int AB>
__device__ __forceinline__ void compute_chunk(
    uint32_t st, uint32_t aBase, uint32_t bBase, float (&acc)[4][2][4][4])
{
#pragma unroll
    for (int kk = 0; kk < 4; kk++) {
        uint32_t af[2][4];
#pragma unroll
        for (int mi = 0; mi < 2; mi++) {
            ldsm4(af[mi], st + aBase + kk * 32 + (uint32_t)(mi * 16) * TSTRIDE);
            tf32r4(af[mi]);
        }
#pragma unroll
        for (int g = 0; g < NG; g++) {
            uint32_t bf[2][4];
#pragma unroll
            for (int jp = 0; jp < 2; jp++) {
                ldsm4(bf[jp], st + bBase + (uint32_t)g * TILE_B + kk * 32
                               + (uint32_t)(jp * 16) * TSTRIDE);
                tf32r4(bf[jp]);
            }
#pragma unroll
            for (int jp = 0; jp < 2; jp++)
#pragma unroll
                for (int mi = 0; mi < 2; mi++) {
                    mma_tf32(acc[AB + g][mi][2 * jp],
                             af[mi][0], af[mi][1], af[mi][2], af[mi][3],
                             bf[jp][0], bf[jp][1]);
                    mma_tf32(acc[AB + g][mi][2 * jp + 1],
                             af[mi][0], af[mi][1], af[mi][2], af[mi][3],
                             bf[jp][2], bf[jp][3]);
                }
        }
    }
}

// ---------------- Kernel B: fused 4-gate TF32 GEMM + sLSTM pointwise -------
__global__ __launch_bounds__(NTHR, 2) void gemm_fused_kernel(
    const float* __restrict__ rec,
    const float* __restrict__ cell, const float* __restrict__ normst,
    const float* __restrict__ maxst,
    const float* __restrict__ wi_in, const float* __restrict__ wf_in,
    const float* __restrict__ wz_in, const float* __restrict__ wo_in,
    const float* __restrict__ wi_st, const float* __restrict__ wf_st,
    const float* __restrict__ wz_st, const float* __restrict__ wo_st,
    const float* __restrict__ bi, const float* __restrict__ bf_,
    const float* __restrict__ bz, const float* __restrict__ bo,
    float* __restrict__ dout)
{
    extern __shared__ __align__(1024) char smem[];
    const uint32_t sbase = smem_u32(smem);
    const int tid  = threadIdx.x;
    const int wid  = tid >> 5;
    const int lane = tid & 31;

    const int nh = blockIdx.z;
    const int m0 = blockIdx.y * BM;
    const int n0 = blockIdx.x * BN;
    const size_t woff = (size_t)nh * HSZ * HSZ;

    // loader for chunk c in [0,96): phase = c/32 selects A source + gate set
    auto do_load = [&](int c) {
        const int phase = c >> 5;
        const int kt    = (c & 31) * BK;
        const uint32_t st = sbase + (uint32_t)(c & 1) * STAGE_B;
        const float* A;
        const float* Wg[4];
        int ng;
        if (phase == 0)      { A = g_xact; Wg[0] = wi_in + woff; Wg[1] = wf_in + woff; Wg[2] = 0; Wg[3] = 0; ng = 2; }
        else if (phase == 1) { A = g_xn;   Wg[0] = wz_in + woff; Wg[1] = wo_in + woff; Wg[2] = 0; Wg[3] = 0; ng = 2; }
        else                 { A = rec;    Wg[0] = wi_st + woff; Wg[1] = wf_st + woff;
                               Wg[2] = wz_st + woff; Wg[3] = wo_st + woff; ng = 4; }
#pragma unroll
        for (int t = 0; t < 4; t++) {
            const int idx = tid + t * NTHR;        // 0..511
            const int row = idx >> 3, sec = idx & 7;
            cp16(st + OFF_A + (uint32_t)row * TSTRIDE + sec * 16,
                 A + (size_t)(m0 + row) * HDIM + (size_t)nh * HSZ + kt + sec * 4);
        }
#pragma unroll
        for (int g = 0; g < 4; g++) {
            if (g < ng) {
#pragma unroll
                for (int t = 0; t < 4; t++) {
                    const int idx = tid + t * NTHR;
                    const int row = idx >> 3, sec = idx & 7;
                    cp16(st + OFF_B + (uint32_t)g * TILE_B + (uint32_t)row * TSTRIDE + sec * 16,
                         Wg[g] + (size_t)(n0 + row) * HSZ + kt + sec * 4);
                }
            }
        }
        asm volatile("cp.async.commit_group;");
    };

    // warp tiling: 2 warps along M (32 rows), 2 along N (32 cols)
    const int wm = wid & 1;
    const int wn = wid >> 1;
    const int grp = lane >> 2;
    const int thr = lane & 3;

    const uint32_t aBase = OFF_A
        + (uint32_t)(wm * 32 + (lane & 15)) * TSTRIDE + (uint32_t)(lane >> 4) * 16;
    const uint32_t bBase =
        (uint32_t)(wn * 32 + (lane & 7) + (lane >> 4) * 8) * TSTRIDE
        + (uint32_t)((lane >> 3) & 1) * 16;   // relative to OFF_B + g*TILE_B

    float acc[4][2][4][4];
#pragma unroll
    for (int g = 0; g < 4; g++)
#pragma unroll
        for (int mi = 0; mi < 2; mi++)
#pragma unroll
            for (int j = 0; j < 4; j++)
#pragma unroll
                for (int q = 0; q < 4; q++) acc[g][mi][j][q] = 0.f;

    do_load(0);

#pragma unroll 1
    for (int c = 0; c < 32; c++) {
        asm volatile("cp.async.wait_group 0;");
        __syncthreads();
        do_load(c + 1);
        compute_chunk<2, 0>(sbase + (uint32_t)(c & 1) * STAGE_B, aBase, OFF_B + bBase, acc);
    }
#pragma unroll 1
    for (int c = 32; c < 64; c++) {
        asm volatile("cp.async.wait_group 0;");
        __syncthreads();
        do_load(c + 1);
        compute_chunk<2, 2>(sbase + (uint32_t)(c & 1) * STAGE_B, aBase, OFF_B + bBase, acc);
    }
#pragma unroll 1
    for (int c = 64; c < 96; c++) {
        asm volatile("cp.async.wait_group 0;");
        __syncthreads();
        if (c + 1 < 96) do_load(c + 1);
        compute_chunk<4, 0>(sbase + (uint32_t)(c & 1) * STAGE_B, aBase, OFF_B + bBase, acc);
    }

    // ---- fused epilogue: bias + sLSTM gate math + state writes ----
    const size_t BH = (size_t)BATCH * HDIM;
    float* outY = dout + 4 * BH;
    float* outC = dout + 5 * BH;
    float* outN = dout + 6 * BH;
    float* outM = dout + 7 * BH;

#pragma unroll
    for (int mi = 0; mi < 2; mi++) {
        const int row0 = m0 + wm * 32 + mi * 16 + grp;
        const int row1 = row0 + 8;
#pragma unroll
        for (int j = 0; j < 4; j++) {
            const int col = n0 + wn * 32 + j * 8 + thr * 2;
            const int h   = nh * HSZ + col;
            const float2 biv = *(const float2*)(bi  + h);
            const float2 bfv = *(const float2*)(bf_ + h);
            const float2 bzv = *(const float2*)(bz  + h);
            const float2 bov = *(const float2*)(bo  + h);

            const size_t o0 = (size_t)row0 * HDIM + h;
            const size_t o1 = (size_t)row1 * HDIM + h;
            const float2 cv0 = *(const float2*)(cell   + o0);
            const float2 nv0 = *(const float2*)(normst + o0);
            const float2 mv0 = *(const float2*)(maxst  + o0);
            const float2 cv1 = *(const float2*)(cell   + o1);
            const float2 nv1 = *(const float2*)(normst + o1);
            const float2 mv1 = *(const float2*)(maxst  + o1);

            float y0, y1, y2, y3, cn0, cn1, cn2, cn3;
            float nn0, nn1, nn2, nn3, mn0, mn1, mn2, mn3;
            slstm1(acc[0][mi][j][0] + biv.x, acc[1][mi][j][0] + bfv.x,
                   acc[2][mi][j][0] + bzv.x, acc[3][mi][j][0] + bov.x,
                   cv0.x, nv0.x, mv0.x, y0, cn0, nn0, mn0);
            slstm1(acc[0][mi][j][1] + biv.y, acc[1][mi][j][1] + bfv.y,
                   acc[2][mi][j][1] + bzv.y, acc[3][mi][j][1] + bov.y,
                   cv0.y, nv0.y, mv0.y, y1, cn1, nn1, mn1);
            slstm1(acc[0][mi][j][2] + biv.x, acc[1][mi][j][2] + bfv.x,
                   acc[2][mi][j][2] + bzv.x, acc[3][mi][j][2] + bov.x,
                   cv1.x, nv1.x, mv1.x, y2, cn2, nn2, mn2);
            slstm1(acc[0][mi][j][3] + biv.y, acc[1][mi][j][3] + bfv.y,
                   acc[2][mi][j][3] + bzv.y, acc[3][mi][j][3] + bov.y,
                   cv1.y, nv1.y, mv1.y, y3, cn3, nn3, mn3);

            *(float2*)(outY + o0) = make_float2(y0, y1);
            *(float2*)(outC + o0) = make_float2(cn0, cn1);
            *(float2*)(outN + o0) = make_float2(nn0, nn1);
            *(float2*)(outM + o0) = make_float2(mn0, mn1);
            *(float2*)(outY + o1) = make_float2(y2, y3);
            *(float2*)(outC + o1) = make_float2(cn2, cn3);
            *(float2*)(outN + o1) = make_float2(nn2, nn3);
            *(float2*)(outM + o1) = make_float2(mn2, mn3);
        }
    }
}

// ---------------- Kernel C: group norm + residual --------------------------
__global__ __launch_bounds__(256) void gn_kernel(
    const float* __restrict__ x, const float* __restrict__ gn_w,
    const float* __restrict__ gn_b, float* __restrict__ dout)
{
    const int blk = blockIdx.x;
    const int b = blk >> 2, n = blk & 3;
    const int tid = threadIdx.x;
    const size_t BH = (size_t)BATCH * HDIM;
    const size_t base = (size_t)b * HDIM + n * HSZ;
    const int c = tid * 4;

    const float* y = dout + 4 * BH;
    float4 yv = *(const float4*)(y + base + c);

    float s  = yv.x + yv.y + yv.z + yv.w;
    float sq = yv.x * yv.x + yv.y * yv.y + yv.z * yv.z + yv.w * yv.w;

    __shared__ float rs[8], rq[8];
    float ws = warpSum(s), wq = warpSum(sq);
    if ((tid & 31) == 0) { rs[tid >> 5] = ws; rq[tid >> 5] = wq; }
    __syncthreads();
    float ts = 0.f, tq = 0.f;
#pragma unroll
    for (int i = 0; i < 8; i++) { ts += rs[i]; tq += rq[i]; }
    const float mean = ts * (1.f / HSZ);
    const float var  = tq * (1.f / HSZ) - mean * mean;
    const float rstd = rsqrtf(var + 1e-5f);

    const int h = n * HSZ + c;
    float4 gw = *(const float4*)(gn_w + h);
    float4 gb = *(const float4*)(gn_b + h);
    float4 xs = *(const float4*)(x + base + c);

    float4 ot;
    ot.x = (yv.x - mean) * rstd * gw.x + gb.x + xs.x;
    ot.y = (yv.y - mean) * rstd * gw.y + gb.y + xs.y;
    ot.z = (yv.z - mean) * rstd * gw.z + gb.z + xs.z;
    ot.w = (yv.w - mean) * rstd * gw.w + gb.w + xs.w;

    *(float4*)(dout + base + c) = ot;
}

// ---------------- launch -----------------------------------------------------
extern "C" void kernel_launch(void* const* d_in, const int* in_sizes, int n_in,
                              void* d_out, int out_size)
{
    const float* x      = (const float*)d_in[0];
    const float* cs     = (const float*)d_in[1];
    const float* rec    = (const float*)d_in[2];
    const float* cell   = (const float*)d_in[3];
    const float* normst = (const float*)d_in[4];
    const float* maxst  = (const float*)d_in[5];
    const float* ln_w   = (const float*)d_in[6];
    const float* conv_w = (const float*)d_in[7];
    const float* conv_b = (const float*)d_in[8];
    const float* wi_in  = (const float*)d_in[9];
    const float* wf_in  = (const float*)d_in[10];
    const float* wz_in  = (const float*)d_in[11];
    const float* wo_in  = (const float*)d_in[12];
    const float* wi_st  = (const float*)d_in[13];
    const float* wf_st  = (const float*)d_in[14];
    const float* wz_st  = (const float*)d_in[15];
    const float* wo_st  = (const float*)d_in[16];
    const float* bi     = (const float*)d_in[17];
    const float* bf_    = (const float*)d_in[18];
    const float* bz     = (const float*)d_in[19];
    const float* bo     = (const float*)d_in[20];
    const float* gn_w   = (const float*)d_in[21];
    const float* gn_b   = (const float*)d_in[22];
    float* out = (float*)d_out;

    static int smem_set = 0;
    if (!smem_set) {
        cudaFuncSetAttribute(gemm_fused_kernel,
                             cudaFuncAttributeMaxDynamicSharedMemorySize, SMEM_B);
        smem_set = 1;
    }

    ln_conv_kernel<<<BATCH, 256>>>(x, cs, ln_w, conv_w, conv_b,
                                   out + (size_t)BATCH * HDIM);

    dim3 grid(HSZ / BN, BATCH / BM, NHEAD);
    gemm_fused_kernel<<<grid, NTHR, SMEM_B>>>(rec, cell, normst, maxst,
                                              wi_in, wf_in, wz_in, wo_in,
                                              wi_st, wf_st, wz_st, wo_st,
                                              bi, bf_, bz, bo, out);

    gn_kernel<<<BATCH * NHEAD, 256>>>(x, gn_w, gn_b, out);
}

// round 16
// speedup vs baseline: 1.0027x; 1.0027x over previous
#include <cuda_runtime.h>
#include <cuda_bf16.h>
#include <math.h>
#include <stdint.h>

#define BATCH 2048
#define HDIM  4096
#define NHEAD 4
#define HSZ   1024

#define BM 64
#define BN 64
#define BK 32              // fp32 elems per K-chunk (128B data rows)
#define NTHR 128           // 4 warps, 32x32 per warp, 4 gates

#define TSTRIDE 144        // 128B data + 16B pad; LDSM conflict-free
#define TILE_B  (64 * TSTRIDE)               // 9216
#define STAGE_B (5 * TILE_B)                 // A + 4x B = 46080
#define SMEM_B  (2 * STAGE_B)                // 92160 (x2 CTAs/SM = 180KB)

#define OFF_A 0
#define OFF_B TILE_B

// ---------------- scratch (device globals; no runtime allocation) ----------
__device__ __align__(16) float g_xn   [(size_t)BATCH * HDIM];
__device__ __align__(16) float g_xact [(size_t)BATCH * HDIM];

// ---------------- helpers ---------------------------------------------------
__device__ __forceinline__ float warpSum(float v) {
#pragma unroll
    for (int o = 16; o > 0; o >>= 1) v += __shfl_down_sync(0xffffffffu, v, o);
    return v;
}

__device__ __forceinline__ uint32_t smem_u32(const void* p) {
    uint32_t a;
    asm("{ .reg .u64 t; cvta.to.shared.u64 t, %1; cvt.u32.u64 %0, t; }"
        : "=r"(a) : "l"(p));
    return a;
}

__device__ __forceinline__ void cp16(uint32_t saddr, const void* gaddr) {
    asm volatile("cp.async.cg.shared.global [%0], [%1], 16;"
                 :: "r"(saddr), "l"(gaddr));
}

__device__ __forceinline__ float tf32r(float x) {
    uint32_t u;
    asm("cvt.rna.tf32.f32 %0, %1;" : "=r"(u) : "f"(x));
    return __uint_as_float(u);
}

__device__ __forceinline__ void tf32r4(uint32_t* r) {
#pragma unroll
    for (int i = 0; i < 4; i++)
        asm("cvt.rna.tf32.f32 %0, %1;" : "=r"(r[i]) : "f"(__uint_as_float(r[i])));
}

__device__ __forceinline__ void ldsm4(uint32_t* r, uint32_t a) {
    asm volatile("ldmatrix.sync.aligned.m8n8.x4.shared.b16 {%0,%1,%2,%3}, [%4];"
                 : "=r"(r[0]), "=r"(r[1]), "=r"(r[2]), "=r"(r[3]) : "r"(a));
}

__device__ __forceinline__ void mma_tf32(float* c, uint32_t a0, uint32_t a1,
                                         uint32_t a2, uint32_t a3,
                                         uint32_t b0, uint32_t b1) {
    asm volatile(
        "mma.sync.aligned.m16n8k8.row.col.f32.tf32.tf32.f32 "
        "{%0,%1,%2,%3}, {%4,%5,%6,%7}, {%8,%9}, {%0,%1,%2,%3};"
        : "+f"(c[0]), "+f"(c[1]), "+f"(c[2]), "+f"(c[3])
        : "r"(a0), "r"(a1), "r"(a2), "r"(a3), "r"(b0), "r"(b1));
}

// gate elementwise math (identical formulas to previous gate_kernel)
__device__ __forceinline__ void slstm1(float iv, float fv, float zv, float ov,
                                       float cv, float nv, float mv,
                                       float& y, float& cn, float& nn, float& mn)
{
    float lsf  = fminf(fv, 0.f) - log1pf(expf(-fabsf(fv)));
    float lfm  = mv + lsf;
    float mnew = fmaxf(iv, lfm);
    float ig = expf(iv  - mnew);
    float fg = expf(lfm - mnew);
    cn = fg * cv + ig * tanhf(zv);
    nn = fg * nv + ig;
    float so = 1.f / (1.f + expf(-ov));
    y  = so * cn / (nn + 1e-6f);
    mn = mnew;
}

// ---------------- Kernel A: layernorm + conv + silu + tf32 emit ------------
__global__ __launch_bounds__(256) void ln_conv_kernel(
    const float* __restrict__ x, const float* __restrict__ cs,
    const float* __restrict__ ln_w, const float* __restrict__ conv_w,
    const float* __restrict__ conv_b, float* __restrict__ out_ncs)
{
    const int b   = blockIdx.x;
    const int tid = threadIdx.x;
    const float* xr = x + (size_t)b * HDIM;

    float4 xv[4];
    float s = 0.f, sq = 0.f;
#pragma unroll
    for (int i = 0; i < 4; i++) {
        xv[i] = *(const float4*)(xr + (size_t)(tid + i * 256) * 4);
        s  += xv[i].x + xv[i].y + xv[i].z + xv[i].w;
        sq += xv[i].x * xv[i].x + xv[i].y * xv[i].y + xv[i].z * xv[i].z + xv[i].w * xv[i].w;
    }
    __shared__ float rs[8], rq[8];
    float ws = warpSum(s), wq = warpSum(sq);
    if ((tid & 31) == 0) { rs[tid >> 5] = ws; rq[tid >> 5] = wq; }
    __syncthreads();
    float ts = 0.f, tq = 0.f;
#pragma unroll
    for (int i = 0; i < 8; i++) { ts += rs[i]; tq += rq[i]; }
    const float mean = ts * (1.f / HDIM);
    const float var  = tq * (1.f / HDIM) - mean * mean;
    const float rstd = rsqrtf(var + 1e-5f);

    const float* csb = cs      + (size_t)b * 3 * HDIM;
    float*       ncs = out_ncs + (size_t)b * 3 * HDIM;

#pragma unroll
    for (int i = 0; i < 4; i++) {
        const int c = (tid + i * 256) * 4;
        float4 lw = *(const float4*)(ln_w + c);
        float4 xn;
        xn.x = (xv[i].x - mean) * rstd * lw.x;
        xn.y = (xv[i].y - mean) * rstd * lw.y;
        xn.z = (xv[i].z - mean) * rstd * lw.z;
        xn.w = (xv[i].w - mean) * rstd * lw.w;

        float4 c0 = *(const float4*)(csb + c);
        float4 c1 = *(const float4*)(csb + HDIM + c);
        float4 c2 = *(const float4*)(csb + 2 * HDIM + c);
        float4 cb = *(const float4*)(conv_b + c);
        float4 w0 = *(const float4*)(conv_w + (size_t)(c + 0) * 4);
        float4 w1 = *(const float4*)(conv_w + (size_t)(c + 1) * 4);
        float4 w2 = *(const float4*)(conv_w + (size_t)(c + 2) * 4);
        float4 w3 = *(const float4*)(conv_w + (size_t)(c + 3) * 4);

        float4 xc;
        xc.x = c0.x * w0.x + c1.x * w0.y + c2.x * w0.z + xn.x * w0.w + cb.x;
        xc.y = c0.y * w1.x + c1.y * w1.y + c2.y * w1.z + xn.y * w1.w + cb.y;
        xc.z = c0.z * w2.x + c1.z * w2.y + c2.z * w2.z + xn.z * w2.w + cb.z;
        xc.w = c0.w * w3.x + c1.w * w3.y + c2.w * w3.z + xn.w * w3.w + cb.w;

        float4 xa;
        xa.x = xc.x / (1.f + expf(-xc.x));
        xa.y = xc.y / (1.f + expf(-xc.y));
        xa.z = xc.z / (1.f + expf(-xc.z));
        xa.w = xc.w / (1.f + expf(-xc.w));

        float4 xnr, xar;
        xnr.x = tf32r(xn.x); xnr.y = tf32r(xn.y); xnr.z = tf32r(xn.z); xnr.w = tf32r(xn.w);
        xar.x = tf32r(xa.x); xar.y = tf32r(xa.y); xar.z = tf32r(xa.z); xar.w = tf32r(xa.w);

        const size_t off = (size_t)b * HDIM + c;
        *(float4*)(g_xn   + off) = xnr;
        *(float4*)(g_xact + off) = xar;

        *(float4*)(ncs + c)            = c1;
        *(float4*)(ncs + HDIM + c)     = c2;
        *(float4*)(ncs + 2 * HDIM + c) = xn;
    }
}

// ---------------- fused GEMM compute chunk (compile-time gate set) ----------
template<int NG, int AB>
__device__ __forceinline__ void compute_chunk(
    uint32_t st, uint32_t aBase, uint32_t bBase, float (&acc)[4][2][4][4])
{
#pragma unroll
    for (int kk = 0; kk < 4; kk++) {
        uint32_t af[2][4];
#pragma unroll
        for (int mi = 0; mi < 2; mi++) {
            ldsm4(af[mi], st + aBase + kk * 32 + (uint32_t)(mi * 16) * TSTRIDE);
            tf32r4(af[mi]);
        }
#pragma unroll
        for (int g = 0; g < NG; g++) {
            uint32_t bf[2][4];
#pragma unroll
            for (int jp = 0; jp < 2; jp++) {
                ldsm4(bf[jp], st + bBase + (uint32_t)g * TILE_B + kk * 32
                               + (uint32_t)(jp * 16) * TSTRIDE);
                tf32r4(bf[jp]);
            }
#pragma unroll
            for (int jp = 0; jp < 2; jp++)
#pragma unroll
                for (int mi = 0; mi < 2; mi++) {
                    mma_tf32(acc[AB + g][mi][2 * jp],
                             af[mi][0], af[mi][1], af[mi][2], af[mi][3],
                             bf[jp][0], bf[jp][1]);
                    mma_tf32(acc[AB + g][mi][2 * jp + 1],
                             af[mi][0], af[mi][1], af[mi][2], af[mi][3],
                             bf[jp][2], bf[jp][3]);
                }
        }
    }
}

// ---------------- Kernel B: fused 4-gate TF32 GEMM + sLSTM pointwise -------
__global__ __launch_bounds__(NTHR, 2) void gemm_fused_kernel(
    const float* __restrict__ rec,
    const float* __restrict__ cell, const float* __restrict__ normst,
    const float* __restrict__ maxst,
    const float* __restrict__ wi_in, const float* __restrict__ wf_in,
    const float* __restrict__ wz_in, const float* __restrict__ wo_in,
    const float* __restrict__ wi_st, const float* __restrict__ wf_st,
    const float* __restrict__ wz_st, const float* __restrict__ wo_st,
    const float* __restrict__ bi, const float* __restrict__ bf_,
    const float* __restrict__ bz, const float* __restrict__ bo,
    float* __restrict__ dout)
{
    extern __shared__ __align__(1024) char smem[];
    const uint32_t sbase = smem_u32(smem);
    const int tid  = threadIdx.x;
    const int wid  = tid >> 5;
    const int lane = tid & 31;

    const int nh = blockIdx.z;
    const int m0 = blockIdx.y * BM;
    const int n0 = blockIdx.x * BN;
    const size_t woff = (size_t)nh * HSZ * HSZ;

    // loader for chunk c in [0,96): phase = c/32 selects A source + gate set
    auto do_load = [&](int c) {
        const int phase = c >> 5;
        const int kt    = (c & 31) * BK;
        const uint32_t st = sbase + (uint32_t)(c & 1) * STAGE_B;
        const float* A;
        const float* Wg[4];
        int ng;
        if (phase == 0)      { A = g_xact; Wg[0] = wi_in + woff; Wg[1] = wf_in + woff; Wg[2] = 0; Wg[3] = 0; ng = 2; }
        else if (phase == 1) { A = g_xn;   Wg[0] = wz_in + woff; Wg[1] = wo_in + woff; Wg[2] = 0; Wg[3] = 0; ng = 2; }
        else                 { A = rec;    Wg[0] = wi_st + woff; Wg[1] = wf_st + woff;
                               Wg[2] = wz_st + woff; Wg[3] = wo_st + woff; ng = 4; }
#pragma unroll
        for (int t = 0; t < 4; t++) {
            const int idx = tid + t * NTHR;        // 0..511
            const int row = idx >> 3, sec = idx & 7;
            cp16(st + OFF_A + (uint32_t)row * TSTRIDE + sec * 16,
                 A + (size_t)(m0 + row) * HDIM + (size_t)nh * HSZ + kt + sec * 4);
        }
#pragma unroll
        for (int g = 0; g < 4; g++) {
            if (g < ng) {
#pragma unroll
                for (int t = 0; t < 4; t++) {
                    const int idx = tid + t * NTHR;
                    const int row = idx >> 3, sec = idx & 7;
                    cp16(st + OFF_B + (uint32_t)g * TILE_B + (uint32_t)row * TSTRIDE + sec * 16,
                         Wg[g] + (size_t)(n0 + row) * HSZ + kt + sec * 4);
                }
            }
        }
        asm volatile("cp.async.commit_group;");
    };

    // warp tiling: 2 warps along M (32 rows), 2 along N (32 cols)
    const int wm = wid & 1;
    const int wn = wid >> 1;
    const int grp = lane >> 2;
    const int thr = lane & 3;

    const uint32_t aBase = OFF_A
        + (uint32_t)(wm * 32 + (lane & 15)) * TSTRIDE + (uint32_t)(lane >> 4) * 16;
    const uint32_t bBase =
        (uint32_t)(wn * 32 + (lane & 7) + (lane >> 4) * 8) * TSTRIDE
        + (uint32_t)((lane >> 3) & 1) * 16;   // relative to OFF_B + g*TILE_B

    float acc[4][2][4][4];
#pragma unroll
    for (int g = 0; g < 4; g++)
#pragma unroll
        for (int mi = 0; mi < 2; mi++)
#pragma unroll
            for (int j = 0; j < 4; j++)
#pragma unroll
                for (int q = 0; q < 4; q++) acc[g][mi][j][q] = 0.f;

    do_load(0);

#pragma unroll 1
    for (int c = 0; c < 32; c++) {
        asm volatile("cp.async.wait_group 0;");
        __syncthreads();
        do_load(c + 1);
        compute_chunk<2, 0>(sbase + (uint32_t)(c & 1) * STAGE_B, aBase, OFF_B + bBase, acc);
    }
#pragma unroll 1
    for (int c = 32; c < 64; c++) {
        asm volatile("cp.async.wait_group 0;");
        __syncthreads();
        do_load(c + 1);
        compute_chunk<2, 2>(sbase + (uint32_t)(c & 1) * STAGE_B, aBase, OFF_B + bBase, acc);
    }
#pragma unroll 1
    for (int c = 64; c < 96; c++) {
        asm volatile("cp.async.wait_group 0;");
        __syncthreads();
        if (c + 1 < 96) do_load(c + 1);
        compute_chunk<4, 0>(sbase + (uint32_t)(c & 1) * STAGE_B, aBase, OFF_B + bBase, acc);
    }

    // ---- fused epilogue: bias + sLSTM gate math + state writes ----
    const size_t BH = (size_t)BATCH * HDIM;
    float* outY = dout + 4 * BH;
    float* outC = dout + 5 * BH;
    float* outN = dout + 6 * BH;
    float* outM = dout + 7 * BH;

#pragma unroll
    for (int mi = 0; mi < 2; mi++) {
        const int row0 = m0 + wm * 32 + mi * 16 + grp;
        const int row1 = row0 + 8;
#pragma unroll
        for (int j = 0; j < 4; j++) {
            const int col = n0 + wn * 32 + j * 8 + thr * 2;
            const int h   = nh * HSZ + col;
            const float2 biv = *(const float2*)(bi  + h);
            const float2 bfv = *(const float2*)(bf_ + h);
            const float2 bzv = *(const float2*)(bz  + h);
            const float2 bov = *(const float2*)(bo  + h);

            const size_t o0 = (size_t)row0 * HDIM + h;
            const size_t o1 = (size_t)row1 * HDIM + h;
            const float2 cv0 = *(const float2*)(cell   + o0);
            const float2 nv0 = *(const float2*)(normst + o0);
            const float2 mv0 = *(const float2*)(maxst  + o0);
            const float2 cv1 = *(const float2*)(cell   + o1);
            const float2 nv1 = *(const float2*)(normst + o1);
            const float2 mv1 = *(const float2*)(maxst  + o1);

            float y0, y1, y2, y3, cn0, cn1, cn2, cn3;
            float nn0, nn1, nn2, nn3, mn0, mn1, mn2, mn3;
            slstm1(acc[0][mi][j][0] + biv.x, acc[1][mi][j][0] + bfv.x,
                   acc[2][mi][j][0] + bzv.x, acc[3][mi][j][0] + bov.x,
                   cv0.x, nv0.x, mv0.x, y0, cn0, nn0, mn0);
            slstm1(acc[0][mi][j][1] + biv.y, acc[1][mi][j][1] + bfv.y,
                   acc[2][mi][j][1] + bzv.y, acc[3][mi][j][1] + bov.y,
                   cv0.y, nv0.y, mv0.y, y1, cn1, nn1, mn1);
            slstm1(acc[0][mi][j][2] + biv.x, acc[1][mi][j][2] + bfv.x,
                   acc[2][mi][j][2] + bzv.x, acc[3][mi][j][2] + bov.x,
                   cv1.x, nv1.x, mv1.x, y2, cn2, nn2, mn2);
            slstm1(acc[0][mi][j][3] + biv.y, acc[1][mi][j][3] + bfv.y,
                   acc[2][mi][j][3] + bzv.y, acc[3][mi][j][3] + bov.y,
                   cv1.y, nv1.y, mv1.y, y3, cn3, nn3, mn3);

            *(float2*)(outY + o0) = make_float2(y0, y1);
            *(float2*)(outC + o0) = make_float2(cn0, cn1);
            *(float2*)(outN + o0) = make_float2(nn0, nn1);
            *(float2*)(outM + o0) = make_float2(mn0, mn1);
            *(float2*)(outY + o1) = make_float2(y2, y3);
            *(float2*)(outC + o1) = make_float2(cn2, cn3);
            *(float2*)(outN + o1) = make_float2(nn2, nn3);
            *(float2*)(outM + o1) = make_float2(mn2, mn3);
        }
    }
}

// ---------------- Kernel C: group norm + residual --------------------------
__global__ __launch_bounds__(256) void gn_kernel(
    const float* __restrict__ x, const float* __restrict__ gn_w,
    const float* __restrict__ gn_b, float* __restrict__ dout)
{
    const int blk = blockIdx.x;
    const int b = blk >> 2, n = blk & 3;
    const int tid = threadIdx.x;
    const size_t BH = (size_t)BATCH * HDIM;
    const size_t base = (size_t)b * HDIM + n * HSZ;
    const int c = tid * 4;

    const float* y = dout + 4 * BH;
    float4 yv = *(const float4*)(y + base + c);

    float s  = yv.x + yv.y + yv.z + yv.w;
    float sq = yv.x * yv.x + yv.y * yv.y + yv.z * yv.z + yv.w * yv.w;

    __shared__ float rs[8], rq[8];
    float ws = warpSum(s), wq = warpSum(sq);
    if ((tid & 31) == 0) { rs[tid >> 5] = ws; rq[tid >> 5] = wq; }
    __syncthreads();
    float ts = 0.f, tq = 0.f;
#pragma unroll
    for (int i = 0; i < 8; i++) { ts += rs[i]; tq += rq[i]; }
    const float mean = ts * (1.f / HSZ);
    const float var  = tq * (1.f / HSZ) - mean * mean;
    const float rstd = rsqrtf(var + 1e-5f);

    const int h = n * HSZ + c;
    float4 gw = *(const float4*)(gn_w + h);
    float4 gb = *(const float4*)(gn_b + h);
    float4 xs = *(const float4*)(x + base + c);

    float4 ot;
    ot.x = (yv.x - mean) * rstd * gw.x + gb.x + xs.x;
    ot.y = (yv.y - mean) * rstd * gw.y + gb.y + xs.y;
    ot.z = (yv.z - mean) * rstd * gw.z + gb.z + xs.z;
    ot.w = (yv.w - mean) * rstd * gw.w + gb.w + xs.w;

    *(float4*)(dout + base + c) = ot;
}

// ---------------- launch -----------------------------------------------------
extern "C" void kernel_launch(void* const* d_in, const int* in_sizes, int n_in,
                              void* d_out, int out_size)
{
    const float* x      = (const float*)d_in[0];
    const float* cs     = (const float*)d_in[1];
    const float* rec    = (const float*)d_in[2];
    const float* cell   = (const float*)d_in[3];
    const float* normst = (const float*)d_in[4];
    const float* maxst  = (const float*)d_in[5];
    const float* ln_w   = (const float*)d_in[6];
    const float* conv_w = (const float*)d_in[7];
    const float* conv_b = (const float*)d_in[8];
    const float* wi_in  = (const float*)d_in[9];
    const float* wf_in  = (const float*)d_in[10];
    const float* wz_in  = (const float*)d_in[11];
    const float* wo_in  = (const float*)d_in[12];
    const float* wi_st  = (const float*)d_in[13];
    const float* wf_st  = (const float*)d_in[14];
    const float* wz_st  = (const float*)d_in[15];
    const float* wo_st  = (const float*)d_in[16];
    const float* bi     = (const float*)d_in[17];
    const float* bf_    = (const float*)d_in[18];
    const float* bz     = (const float*)d_in[19];
    const float* bo     = (const float*)d_in[20];
    const float* gn_w   = (const float*)d_in[21];
    const float* gn_b   = (const float*)d_in[22];
    float* out = (float*)d_out;

    static int smem_set = 0;
    if (!smem_set) {
        cudaFuncSetAttribute(gemm_fused_kernel,
                             cudaFuncAttributeMaxDynamicSharedMemorySize, SMEM_B);
        smem_set = 1;
    }

    ln_conv_kernel<<<BATCH, 256>>>(x, cs, ln_w, conv_w, conv_b,
                                   out + (size_t)BATCH * HDIM);

    dim3 grid(HSZ / BN, BATCH / BM, NHEAD);
    gemm_fused_kernel<<<grid, NTHR, SMEM_B>>>(rec, cell, normst, maxst,
                                              wi_in, wf_in, wz_in, wo_in,
                                              wi_st, wf_st, wz_st, wo_st,
                                              bi, bf_, bz, bo, out);

    gn_kernel<<<BATCH * NHEAD, 256>>>(x, gn_w, gn_b, out);
}

// round 17
// speedup vs baseline: 1.0034x; 1.0007x over previous
#include <cuda_runtime.h>
#include <cuda_bf16.h>
#include <math.h>
#include <stdint.h>

#define BATCH 2048
#define HDIM  4096
#define NHEAD 4
#define HSZ   1024

#define BM 64
#define BN 64
#define BK 32              // fp32 elems per K-chunk (128B data rows)
#define NTHR 128           // 4 warps, 32x32 per warp, 4 gates

#define TSTRIDE 144        // 128B data + 16B pad; LDSM conflict-free
#define TILE_B  (64 * TSTRIDE)               // 9216
#define STAGE_B (5 * TILE_B)                 // A + 4x B = 46080
#define SMEM_B  (2 * STAGE_B)                // 92160 (x2 CTAs/SM = 180KB)

#define OFF_A 0
#define OFF_B TILE_B

// ---------------- scratch (device globals; no runtime allocation) ----------
__device__ __align__(16) float g_xn   [(size_t)BATCH * HDIM];
__device__ __align__(16) float g_xact [(size_t)BATCH * HDIM];

// ---------------- helpers ---------------------------------------------------
__device__ __forceinline__ float warpSum(float v) {
#pragma unroll
    for (int o = 16; o > 0; o >>= 1) v += __shfl_down_sync(0xffffffffu, v, o);
    return v;
}

__device__ __forceinline__ uint32_t smem_u32(const void* p) {
    uint32_t a;
    asm("{ .reg .u64 t; cvta.to.shared.u64 t, %1; cvt.u32.u64 %0, t; }"
        : "=r"(a) : "l"(p));
    return a;
}

__device__ __forceinline__ void cp16(uint32_t saddr, const void* gaddr) {
    asm volatile("cp.async.cg.shared.global [%0], [%1], 16;"
                 :: "r"(saddr), "l"(gaddr));
}

__device__ __forceinline__ float tf32r(float x) {
    uint32_t u;
    asm("cvt.rna.tf32.f32 %0, %1;" : "=r"(u) : "f"(x));
    return __uint_as_float(u);
}

__device__ __forceinline__ void tf32r4(uint32_t* r) {
#pragma unroll
    for (int i = 0; i < 4; i++)
        asm("cvt.rna.tf32.f32 %0, %1;" : "=r"(r[i]) : "f"(__uint_as_float(r[i])));
}

__device__ __forceinline__ void ldsm4(uint32_t* r, uint32_t a) {
    asm volatile("ldmatrix.sync.aligned.m8n8.x4.shared.b16 {%0,%1,%2,%3}, [%4];"
                 : "=r"(r[0]), "=r"(r[1]), "=r"(r[2]), "=r"(r[3]) : "r"(a));
}

__device__ __forceinline__ void mma_tf32(float* c, uint32_t a0, uint32_t a1,
                                         uint32_t a2, uint32_t a3,
                                         uint32_t b0, uint32_t b1) {
    asm volatile(
        "mma.sync.aligned.m16n8k8.row.col.f32.tf32.tf32.f32 "
        "{%0,%1,%2,%3}, {%4,%5,%6,%7}, {%8,%9}, {%0,%1,%2,%3};"
        : "+f"(c[0]), "+f"(c[1]), "+f"(c[2]), "+f"(c[3])
        : "r"(a0), "r"(a1), "r"(a2), "r"(a3), "r"(b0), "r"(b1));
}

// gate elementwise math (identical formulas to previous gate_kernel)
__device__ __forceinline__ void slstm1(float iv, float fv, float zv, float ov,
                                       float cv, float nv, float mv,
                                       float& y, float& cn, float& nn, float& mn)
{
    float lsf  = fminf(fv, 0.f) - log1pf(expf(-fabsf(fv)));
    float lfm  = mv + lsf;
    float mnew = fmaxf(iv, lfm);
    float ig = expf(iv  - mnew);
    float fg = expf(lfm - mnew);
    cn = fg * cv + ig * tanhf(zv);
    nn = fg * nv + ig;
    float so = 1.f / (1.f + expf(-ov));
    y  = so * cn / (nn + 1e-6f);
    mn = mnew;
}

// ---------------- Kernel A: layernorm + conv + silu + tf32 emit ------------
__global__ __launch_bounds__(256) void ln_conv_kernel(
    const float* __restrict__ x, const float* __restrict__ cs,
    const float* __restrict__ ln_w, const float* __restrict__ conv_w,
    const float* __restrict__ conv_b, float* __restrict__ out_ncs)
{
    const int b   = blockIdx.x;
    const int tid = threadIdx.x;
    const float* xr = x + (size_t)b * HDIM;

    float4 xv[4];
    float s = 0.f, sq = 0.f;
#pragma unroll
    for (int i = 0; i < 4; i++) {
        xv[i] = *(const float4*)(xr + (size_t)(tid + i * 256) * 4);
        s  += xv[i].x + xv[i].y + xv[i].z + xv[i].w;
        sq += xv[i].x * xv[i].x + xv[i].y * xv[i].y + xv[i].z * xv[i].z + xv[i].w * xv[i].w;
    }
    __shared__ float rs[8], rq[8];
    float ws = warpSum(s), wq = warpSum(sq);
    if ((tid & 31) == 0) { rs[tid >> 5] = ws; rq[tid >> 5] = wq; }
    __syncthreads();
    float ts = 0.f, tq = 0.f;
#pragma unroll
    for (int i = 0; i < 8; i++) { ts += rs[i]; tq += rq[i]; }
    const float mean = ts * (1.f / HDIM);
    const float var  = tq * (1.f / HDIM) - mean * mean;
    const float rstd = rsqrtf(var + 1e-5f);

    const float* csb = cs      + (size_t)b * 3 * HDIM;
    float*       ncs = out_ncs + (size_t)b * 3 * HDIM;

#pragma unroll
    for (int i = 0; i < 4; i++) {
        const int c = (tid + i * 256) * 4;
        float4 lw = *(const float4*)(ln_w + c);
        float4 xn;
        xn.x = (xv[i].x - mean) * rstd * lw.x;
        xn.y = (xv[i].y - mean) * rstd * lw.y;
        xn.z = (xv[i].z - mean) * rstd * lw.z;
        xn.w = (xv[i].w - mean) * rstd * lw.w;

        float4 c0 = *(const float4*)(csb + c);
        float4 c1 = *(const float4*)(csb + HDIM + c);
        float4 c2 = *(const float4*)(csb + 2 * HDIM + c);
        float4 cb = *(const float4*)(conv_b + c);
        float4 w0 = *(const float4*)(conv_w + (size_t)(c + 0) * 4);
        float4 w1 = *(const float4*)(conv_w + (size_t)(c + 1) * 4);
        float4 w2 = *(const float4*)(conv_w + (size_t)(c + 2) * 4);
        float4 w3 = *(const float4*)(conv_w + (size_t)(c + 3) * 4);

        float4 xc;
        xc.x = c0.x * w0.x + c1.x * w0.y + c2.x * w0.z + xn.x * w0.w + cb.x;
        xc.y = c0.y * w1.x + c1.y * w1.y + c2.y * w1.z + xn.y * w1.w + cb.y;
        xc.z = c0.z * w2.x + c1.z * w2.y + c2.z * w2.z + xn.z * w2.w + cb.z;
        xc.w = c0.w * w3.x + c1.w * w3.y + c2.w * w3.z + xn.w * w3.w + cb.w;

        float4 xa;
        xa.x = xc.x / (1.f + expf(-xc.x));
        xa.y = xc.y / (1.f + expf(-xc.y));
        xa.z = xc.z / (1.f + expf(-xc.z));
        xa.w = xc.w / (1.f + expf(-xc.w));

        float4 xnr, xar;
        xnr.x = tf32r(xn.x); xnr.y = tf32r(xn.y); xnr.z = tf32r(xn.z); xnr.w = tf32r(xn.w);
        xar.x = tf32r(xa.x); xar.y = tf32r(xa.y); xar.z = tf32r(xa.z); xar.w = tf32r(xa.w);

        const size_t off = (size_t)b * HDIM + c;
        *(float4*)(g_xn   + off) = xnr;
        *(float4*)(g_xact + off) = xar;

        *(float4*)(ncs + c)            = c1;
        *(float4*)(ncs + HDIM + c)     = c2;
        *(float4*)(ncs + 2 * HDIM + c) = xn;
    }
}

// ---------------- fused GEMM compute chunk (compile-time gate set) ----------
template<int NG, int AB>
__device__ __forceinline__ void compute_chunk(
    uint32_t st, uint32_t aBase, uint32_t bBase, float (&acc)[4][2][4][4])
{
#pragma unroll
    for (int kk = 0; kk < 4; kk++) {
        uint32_t af[2][4];
#pragma unroll
        for (int mi = 0; mi < 2; mi++) {
            ldsm4(af[mi], st + aBase + kk * 32 + (uint32_t)(mi * 16) * TSTRIDE);
            tf32r4(af[mi]);
        }
#pragma unroll
        for (int g = 0; g < NG; g++) {
            uint32_t bf[2][4];
#pragma unroll
            for (int jp = 0; jp < 2; jp++) {
                ldsm4(bf[jp], st + bBase + (uint32_t)g * TILE_B + kk * 32
                               + (uint32_t)(jp * 16) * TSTRIDE);
                tf32r4(bf[jp]);
            }
#pragma unroll
            for (int jp = 0; jp < 2; jp++)
#pragma unroll
                for (int mi = 0; mi < 2; mi++) {
                    mma_tf32(acc[AB + g][mi][2 * jp],
                             af[mi][0], af[mi][1], af[mi][2], af[mi][3],
                             bf[jp][0], bf[jp][1]);
                    mma_tf32(acc[AB + g][mi][2 * jp + 1],
                             af[mi][0], af[mi][1], af[mi][2], af[mi][3],
                             bf[jp][2], bf[jp][3]);
                }
        }
    }
}

// ---------------- Kernel B: fused 4-gate TF32 GEMM + sLSTM pointwise -------
__global__ __launch_bounds__(NTHR, 2) void gemm_fused_kernel(
    const float* __restrict__ rec,
    const float* __restrict__ cell, const float* __restrict__ normst,
    const float* __restrict__ maxst,
    const float* __restrict__ wi_in, const float* __restrict__ wf_in,
    const float* __restrict__ wz_in, const float* __restrict__ wo_in,
    const float* __restrict__ wi_st, const float* __restrict__ wf_st,
    const float* __restrict__ wz_st, const float* __restrict__ wo_st,
    const float* __restrict__ bi, const float* __restrict__ bf_,
    const float* __restrict__ bz, const float* __restrict__ bo,
    float* __restrict__ dout)
{
    extern __shared__ __align__(1024) char smem[];
    const uint32_t sbase = smem_u32(smem);
    const int tid  = threadIdx.x;
    const int wid  = tid >> 5;
    const int lane = tid & 31;

    const int nh = blockIdx.z;
    const int m0 = blockIdx.y * BM;
    const int n0 = blockIdx.x * BN;
    const size_t woff = (size_t)nh * HSZ * HSZ;

    // loader for chunk c in [0,96): phase = c/32 selects A source + gate set
    auto do_load = [&](int c) {
        const int phase = c >> 5;
        const int kt    = (c & 31) * BK;
        const uint32_t st = sbase + (uint32_t)(c & 1) * STAGE_B;
        const float* A;
        const float* Wg[4];
        int ng;
        if (phase == 0)      { A = g_xact; Wg[0] = wi_in + woff; Wg[1] = wf_in + woff; Wg[2] = 0; Wg[3] = 0; ng = 2; }
        else if (phase == 1) { A = g_xn;   Wg[0] = wz_in + woff; Wg[1] = wo_in + woff; Wg[2] = 0; Wg[3] = 0; ng = 2; }
        else                 { A = rec;    Wg[0] = wi_st + woff; Wg[1] = wf_st + woff;
                               Wg[2] = wz_st + woff; Wg[3] = wo_st + woff; ng = 4; }
#pragma unroll
        for (int t = 0; t < 4; t++) {
            const int idx = tid + t * NTHR;        // 0..511
            const int row = idx >> 3, sec = idx & 7;
            cp16(st + OFF_A + (uint32_t)row * TSTRIDE + sec * 16,
                 A + (size_t)(m0 + row) * HDIM + (size_t)nh * HSZ + kt + sec * 4);
        }
#pragma unroll
        for (int g = 0; g < 4; g++) {
            if (g < ng) {
#pragma unroll
                for (int t = 0; t < 4; t++) {
                    const int idx = tid + t * NTHR;
                    const int row = idx >> 3, sec = idx & 7;
                    cp16(st + OFF_B + (uint32_t)g * TILE_B + (uint32_t)row * TSTRIDE + sec * 16,
                         Wg[g] + (size_t)(n0 + row) * HSZ + kt + sec * 4);
                }
            }
        }
        asm volatile("cp.async.commit_group;");
    };

    // warp tiling: 2 warps along M (32 rows), 2 along N (32 cols)
    const int wm = wid & 1;
    const int wn = wid >> 1;
    const int grp = lane >> 2;
    const int thr = lane & 3;

    const uint32_t aBase = OFF_A
        + (uint32_t)(wm * 32 + (lane & 15)) * TSTRIDE + (uint32_t)(lane >> 4) * 16;
    const uint32_t bBase =
        (uint32_t)(wn * 32 + (lane & 7) + (lane >> 4) * 8) * TSTRIDE
        + (uint32_t)((lane >> 3) & 1) * 16;   // relative to OFF_B + g*TILE_B

    float acc[4][2][4][4];
#pragma unroll
    for (int g = 0; g < 4; g++)
#pragma unroll
        for (int mi = 0; mi < 2; mi++)
#pragma unroll
            for (int j = 0; j < 4; j++)
#pragma unroll
                for (int q = 0; q < 4; q++) acc[g][mi][j][q] = 0.f;

    do_load(0);

#pragma unroll 1
    for (int c = 0; c < 32; c++) {
        asm volatile("cp.async.wait_group 0;");
        __syncthreads();
        do_load(c + 1);
        compute_chunk<2, 0>(sbase + (uint32_t)(c & 1) * STAGE_B, aBase, OFF_B + bBase, acc);
    }
#pragma unroll 1
    for (int c = 32; c < 64; c++) {
        asm volatile("cp.async.wait_group 0;");
        __syncthreads();
        do_load(c + 1);
        compute_chunk<2, 2>(sbase + (uint32_t)(c & 1) * STAGE_B, aBase, OFF_B + bBase, acc);
    }
#pragma unroll 1
    for (int c = 64; c < 96; c++) {
        asm volatile("cp.async.wait_group 0;");
        __syncthreads();
        if (c + 1 < 96) do_load(c + 1);
        compute_chunk<4, 0>(sbase + (uint32_t)(c & 1) * STAGE_B, aBase, OFF_B + bBase, acc);
    }

    // ---- fused epilogue: bias + sLSTM gate math + state writes ----
    const size_t BH = (size_t)BATCH * HDIM;
    float* outY = dout + 4 * BH;
    float* outC = dout + 5 * BH;
    float* outN = dout + 6 * BH;
    float* outM = dout + 7 * BH;

#pragma unroll
    for (int mi = 0; mi < 2; mi++) {
        const int row0 = m0 + wm * 32 + mi * 16 + grp;
        const int row1 = row0 + 8;
#pragma unroll
        for (int j = 0; j < 4; j++) {
            const int col = n0 + wn * 32 + j * 8 + thr * 2;
            const int h   = nh * HSZ + col;
            const float2 biv = *(const float2*)(bi  + h);
            const float2 bfv = *(const float2*)(bf_ + h);
            const float2 bzv = *(const float2*)(bz  + h);
            const float2 bov = *(const float2*)(bo  + h);

            const size_t o0 = (size_t)row0 * HDIM + h;
            const size_t o1 = (size_t)row1 * HDIM + h;
            const float2 cv0 = *(const float2*)(cell   + o0);
            const float2 nv0 = *(const float2*)(normst + o0);
            const float2 mv0 = *(const float2*)(maxst  + o0);
            const float2 cv1 = *(const float2*)(cell   + o1);
            const float2 nv1 = *(const float2*)(normst + o1);
            const float2 mv1 = *(const float2*)(maxst  + o1);

            float y0, y1, y2, y3, cn0, cn1, cn2, cn3;
            float nn0, nn1, nn2, nn3, mn0, mn1, mn2, mn3;
            slstm1(acc[0][mi][j][0] + biv.x, acc[1][mi][j][0] + bfv.x,
                   acc[2][mi][j][0] + bzv.x, acc[3][mi][j][0] + bov.x,
                   cv0.x, nv0.x, mv0.x, y0, cn0, nn0, mn0);
            slstm1(acc[0][mi][j][1] + biv.y, acc[1][mi][j][1] + bfv.y,
                   acc[2][mi][j][1] + bzv.y, acc[3][mi][j][1] + bov.y,
                   cv0.y, nv0.y, mv0.y, y1, cn1, nn1, mn1);
            slstm1(acc[0][mi][j][2] + biv.x, acc[1][mi][j][2] + bfv.x,
                   acc[2][mi][j][2] + bzv.x, acc[3][mi][j][2] + bov.x,
                   cv1.x, nv1.x, mv1.x, y2, cn2, nn2, mn2);
            slstm1(acc[0][mi][j][3] + biv.y, acc[1][mi][j][3] + bfv.y,
                   acc[2][mi][j][3] + bzv.y, acc[3][mi][j][3] + bov.y,
                   cv1.y, nv1.y, mv1.y, y3, cn3, nn3, mn3);

            *(float2*)(outY + o0) = make_float2(y0, y1);
            *(float2*)(outC + o0) = make_float2(cn0, cn1);
            *(float2*)(outN + o0) = make_float2(nn0, nn1);
            *(float2*)(outM + o0) = make_float2(mn0, mn1);
            *(float2*)(outY + o1) = make_float2(y2, y3);
            *(float2*)(outC + o1) = make_float2(cn2, cn3);
            *(float2*)(outN + o1) = make_float2(nn2, nn3);
            *(float2*)(outM + o1) = make_float2(mn2, mn3);
        }
    }
}

// ---------------- Kernel C: group norm + residual --------------------------
__global__ __launch_bounds__(256) void gn_kernel(
    const float* __restrict__ x, const float* __restrict__ gn_w,
    const float* __restrict__ gn_b, float* __restrict__ dout)
{
    const int blk = blockIdx.x;
    const int b = blk >> 2, n = blk & 3;
    const int tid = threadIdx.x;
    const size_t BH = (size_t)BATCH * HDIM;
    const size_t base = (size_t)b * HDIM + n * HSZ;
    const int c = tid * 4;

    const float* y = dout + 4 * BH;
    float4 yv = *(const float4*)(y + base + c);

    float s  = yv.x + yv.y + yv.z + yv.w;
    float sq = yv.x * yv.x + yv.y * yv.y + yv.z * yv.z + yv.w * yv.w;

    __shared__ float rs[8], rq[8];
    float ws = warpSum(s), wq = warpSum(sq);
    if ((tid & 31) == 0) { rs[tid >> 5] = ws; rq[tid >> 5] = wq; }
    __syncthreads();
    float ts = 0.f, tq = 0.f;
#pragma unroll
    for (int i = 0; i < 8; i++) { ts += rs[i]; tq += rq[i]; }
    const float mean = ts * (1.f / HSZ);
    const float var  = tq * (1.f / HSZ) - mean * mean;
    const float rstd = rsqrtf(var + 1e-5f);

    const int h = n * HSZ + c;
    float4 gw = *(const float4*)(gn_w + h);
    float4 gb = *(const float4*)(gn_b + h);
    float4 xs = *(const float4*)(x + base + c);

    float4 ot;
    ot.x = (yv.x - mean) * rstd * gw.x + gb.x + xs.x;
    ot.y = (yv.y - mean) * rstd * gw.y + gb.y + xs.y;
    ot.z = (yv.z - mean) * rstd * gw.z + gb.z + xs.z;
    ot.w = (yv.w - mean) * rstd * gw.w + gb.w + xs.w;

    *(float4*)(dout + base + c) = ot;
}

// ---------------- launch -----------------------------------------------------
extern "C" void kernel_launch(void* const* d_in, const int* in_sizes, int n_in,
                              void* d_out, int out_size)
{
    const float* x      = (const float*)d_in[0];
    const float* cs     = (const float*)d_in[1];
    const float* rec    = (const float*)d_in[2];
    const float* cell   = (const float*)d_in[3];
    const float* normst = (const float*)d_in[4];
    const float* maxst  = (const float*)d_in[5];
    const float* ln_w   = (const float*)d_in[6];
    const float* conv_w = (const float*)d_in[7];
    const float* conv_b = (const float*)d_in[8];
    const float* wi_in  = (const float*)d_in[9];
    const float* wf_in  = (const float*)d_in[10];
    const float* wz_in  = (const float*)d_in[11];
    const float* wo_in  = (const float*)d_in[12];
    const float* wi_st  = (const float*)d_in[13];
    const float* wf_st  = (const float*)d_in[14];
    const float* wz_st  = (const float*)d_in[15];
    const float* wo_st  = (const float*)d_in[16];
    const float* bi     = (const float*)d_in[17];
    const float* bf_    = (const float*)d_in[18];
    const float* bz     = (const float*)d_in[19];
    const float* bo     = (const float*)d_in[20];
    const float* gn_w   = (const float*)d_in[21];
    const float* gn_b   = (const float*)d_in[22];
    float* out = (float*)d_out;

    static int smem_set = 0;
    if (!smem_set) {
        cudaFuncSetAttribute(gemm_fused_kernel,
                             cudaFuncAttributeMaxDynamicSharedMemorySize, SMEM_B);
        smem_set = 1;
    }

    ln_conv_kernel<<<BATCH, 256>>>(x, cs, ln_w, conv_w, conv_b,
                                   out + (size_t)BATCH * HDIM);

    dim3 grid(HSZ / BN, BATCH / BM, NHEAD);
    gemm_fused_kernel<<<grid, NTHR, SMEM_B>>>(rec, cell, normst, maxst,
                                              wi_in, wf_in, wz_in, wo_in,
                                              wi_st, wf_st, wz_st, wo_st,
                                              bi, bf_, bz, bo, out);

    gn_kernel<<<BATCH * NHEAD, 256>>>(x, gn_w, gn_b, out);
}